// round 13
// baseline (speedup 1.0000x reference)
#include <cuda_runtime.h>
#include <cuda_bf16.h>

// Problem shape (fixed by the dataset)
#define HH 64
#define WW 128
#define HW (HH * WW)     // 8192 points per image
#define NPAIR 8          // B*S = 2*4
#define SDIM 4
#define BDIM 2
#define NT 128           // nn block size (4 warps)
#define NTP 256          // prep/prefix/scatter block size

// 1-D sort bins over x
#define NBINS  2048
#define XLO0   (-5.5f)
#define BW     (11.0f / 2048.0f)
#define INV_BW (2048.0f / 11.0f)
#define NLIST  16            // list = side*NPAIR + pair
#define GXN    18            // nn blocks per (dir,pair): 18*256 = 4608 queries
#define QPT    2             // queries per lane (warp covers 64 consecutive sorted queries)

// ---------------- device scratch ----------------
__device__ float4 g_pts[2][NPAIR][HW];   // compacted, unsorted (x,y,z,||p||^2)
__device__ float4 g_sq[NLIST][HW];       // x-sorted, query form (x,y,z,n)
__device__ float4 g_st[NLIST][HW];       // x-sorted, target form (-2x,-2y,-2z,n)
__device__ int    g_bincnt[NLIST][NBINS];
__device__ int    g_bincur[NLIST][NBINS];
__device__ int    g_binstart[NLIST][NBINS + 1];
__device__ int    g_cnt[2][NPAIR];
__device__ float  g_sum[2][NPAIR];
__device__ int    g_part[2][NPAIR];
__device__ int    g_done;

__device__ __forceinline__ int binx(float x) {
    int b = (int)floorf((x - XLO0) * INV_BW);
    return b < 0 ? 0 : (b > NBINS - 1 ? NBINS - 1 : b);
}
__device__ __forceinline__ unsigned long long splat2(float v) {
    unsigned long long r;
    asm("mov.b64 %0, {%1, %1};" : "=l"(r) : "f"(v));
    return r;
}
__device__ __forceinline__ unsigned long long fma2(unsigned long long a,
                                                   unsigned long long b,
                                                   unsigned long long c) {
    unsigned long long d;
    asm("fma.rn.f32x2 %0, %1, %2, %3;" : "=l"(d) : "l"(a), "l"(b), "l"(c));
    return d;
}

// ---------------- 1: zero per-call state ----------------
__global__ void init_kernel() {
    int i = blockIdx.x * blockDim.x + threadIdx.x;   // NLIST*NBINS = 32768 threads
    ((int*)g_bincnt)[i] = 0;
    if (i < 16) {
        ((int*)g_cnt)[i] = 0;
        ((float*)g_sum)[i] = 0.0f;
        ((int*)g_part)[i] = 0;
    }
    if (i == 0) g_done = 0;
}

// ---------------- 2: back-project + compact + x-histogram ----------------
__global__ void prep_kernel(const float* __restrict__ rv,
                            const float* __restrict__ tgt) {
    const int pair = blockIdx.y;
    const int tid = threadIdx.x;
    const int i = blockIdx.x * blockDim.x + tid;   // 0..8191
    const int h = i / WW;
    const int w = i % WW;
    const int wid = tid >> 5, lane = tid & 31;

    const float FOV_DOWN = -0.4363323129985824f;   // -25 deg
    const float FOV      = 0.4886921905584123f;    // 28 deg span
    const float PI_F     = 3.14159265358979323846f;

    float pitch = (1.0f - (h + 0.5f) / (float)HH) * FOV + FOV_DOWN;
    float yaw   = -(((w + 0.5f) / (float)WW) * 2.0f - 1.0f) * PI_F;
    float cp = cosf(pitch), sp = sinf(pitch);
    float cy = cosf(yaw),  sy = sinf(yaw);

    float r = rv[pair * HW + i];
    float px[2], py[2], pz[2];
    bool  pv[2];
    pv[0] = r > 0.0f;
    px[0] = r * cp * cy; py[0] = r * cp * sy; pz[0] = r * sp;

    const float* tp = tgt + (size_t)pair * 4 * HW + i;
    float t0 = tp[0];
    pv[1] = t0 > 0.0f;
    px[1] = tp[HW]; py[1] = tp[2 * HW]; pz[1] = tp[3 * HW];

    __shared__ int s_wcnt[2][NTP / 32];
    __shared__ int s_woff[2][NTP / 32];

    unsigned m[2];
#pragma unroll
    for (int s = 0; s < 2; s++) {
        m[s] = __ballot_sync(0xffffffffu, pv[s]);
        if (lane == 0) s_wcnt[s][wid] = __popc(m[s]);
    }
    __syncthreads();
    if (tid < 2) {   // one atomicAdd per block per side
        int tot = 0;
        int off[NTP / 32];
#pragma unroll
        for (int wv = 0; wv < NTP / 32; wv++) { off[wv] = tot; tot += s_wcnt[tid][wv]; }
        int base = (tot > 0) ? atomicAdd(&g_cnt[tid][pair], tot) : 0;
#pragma unroll
        for (int wv = 0; wv < NTP / 32; wv++) s_woff[tid][wv] = base + off[wv];
    }
    __syncthreads();
#pragma unroll
    for (int s = 0; s < 2; s++) {
        if (pv[s]) {
            int pos = s_woff[s][wid] + __popc(m[s] & ((1u << lane) - 1u));
            float n = px[s] * px[s] + py[s] * py[s] + pz[s] * pz[s];
            g_pts[s][pair][pos] = make_float4(px[s], py[s], pz[s], n);
            atomicAdd(&g_bincnt[s * NPAIR + pair][binx(px[s])], 1);
        }
    }
}

// ---------------- 3: exclusive prefix over bins (one block per list) ----------------
__global__ void prefix_kernel() {
    const int list = blockIdx.x;
    const int t = threadIdx.x;          // 256 threads
    const int PER = NBINS / 256;        // 8 bins per thread
    const int base = t * PER;

    int c[PER];
    int s = 0;
#pragma unroll
    for (int k = 0; k < PER; k++) { c[k] = g_bincnt[list][base + k]; s += c[k]; }

    __shared__ int sh[256];
    sh[t] = s;
    __syncthreads();
    for (int off = 1; off < 256; off <<= 1) {
        int v = (t >= off) ? sh[t - off] : 0;
        __syncthreads();
        sh[t] += v;
        __syncthreads();
    }
    int run = sh[t] - s;   // exclusive
#pragma unroll
    for (int k = 0; k < PER; k++) {
        g_binstart[list][base + k] = run;
        g_bincur[list][base + k] = run;
        run += c[k];
    }
    if (t == 255) g_binstart[list][NBINS] = run;   // = total count
}

// ---------------- 4: scatter into x-sorted order ----------------
__global__ void scatter_kernel() {
    const int side = blockIdx.z, pair = blockIdx.y;
    const int list = side * NPAIR + pair;
    const int i = blockIdx.x * blockDim.x + threadIdx.x;
    if (i >= g_cnt[side][pair]) return;
    float4 p = g_pts[side][pair][i];
    int pos = atomicAdd(&g_bincur[list][binx(p.x)], 1);
    g_sq[list][pos] = p;
    g_st[list][pos] = make_float4(-2.0f * p.x, -2.0f * p.y, -2.0f * p.z, p.w);
}

// ---------------- 5: pipelined two-phase windowed NN + fused finalize ----------------
__global__ void __launch_bounds__(NT) nn_kernel(float* __restrict__ out) {
    const int dir  = blockIdx.z;   // 0: queries = rv pts; 1: queries = target pts
    const int pair = blockIdx.y;
    const int qlist = dir * NPAIR + pair;
    const int tlist = (1 - dir) * NPAIR + pair;
    const int nq = g_cnt[dir][pair];
    const int nt = g_cnt[1 - dir][pair];
    const int tid = threadIdx.x, wid = tid >> 5, lane = tid & 31;
    const int wqbase = blockIdx.x * (NT * QPT) + wid * 64;   // warp's first query

    const float4* __restrict__ st = g_st[tlist];
    const int*    __restrict__ bs = g_binstart[tlist];

    // double-buffered warp-private pair-packed tiles
    __shared__ float4 sP[NT / 32][2][32];
    __shared__ float4 sQ[NT / 32][2][32];

    float dsum = 0.0f;
    if (wqbase < nq && nt > 0) {
        float4 q[QPT];
        unsigned long long ax[QPT], ay[QPT], az[QPT];
        bool valid[QPT];
        float mn0[QPT], mn1[QPT];
#pragma unroll
        for (int k = 0; k < QPT; k++) {
            int qi = wqbase + k * 32 + lane;
            valid[k] = qi < nq;
            q[k] = g_sq[qlist][min(qi, nq - 1)];   // clamp: real coords on all lanes
            ax[k] = splat2(q[k].x); ay[k] = splat2(q[k].y); az[k] = splat2(q[k].z);
            mn0[k] = 3e38f; mn1[k] = 3e38f;
        }

        // ---- pipelined scan of [W0,W1): prefetch chunk i+1 while computing i ----
#define SCAN_RANGE(W0, W1)                                                      \
        {                                                                       \
            int p = 0;                                                          \
            int ja = (W0) + 2 * lane;                                           \
            float4 c0 = (ja     < (W1)) ? st[ja]                                \
                                        : make_float4(0.f, 0.f, 0.f, 3e38f);    \
            float4 c1 = (ja + 1 < (W1)) ? st[ja + 1]                            \
                                        : make_float4(0.f, 0.f, 0.f, 3e38f);    \
            for (int j0 = (W0); j0 < (W1); j0 += 64) {                          \
                sP[wid][p][lane] = make_float4(c0.x, c1.x, c0.y, c1.y);         \
                sQ[wid][p][lane] = make_float4(c0.z, c1.z, c0.w, c1.w);         \
                int jn = j0 + 64 + 2 * lane;                                    \
                if (j0 + 64 < (W1)) {                                           \
                    c0 = (jn     < (W1)) ? st[jn]                               \
                                         : make_float4(0.f, 0.f, 0.f, 3e38f);   \
                    c1 = (jn + 1 < (W1)) ? st[jn + 1]                           \
                                         : make_float4(0.f, 0.f, 0.f, 3e38f);   \
                }                                                               \
                __syncwarp();                                                   \
                const ulonglong2* __restrict__ pP =                             \
                    reinterpret_cast<const ulonglong2*>(sP[wid][p]);            \
                const ulonglong2* __restrict__ pQ =                             \
                    reinterpret_cast<const ulonglong2*>(sQ[wid][p]);            \
                _Pragma("unroll 8")                                             \
                for (int g = 0; g < 32; g++) {                                  \
                    ulonglong2 P = pP[g];                                       \
                    ulonglong2 Q = pQ[g];                                       \
                    _Pragma("unroll")                                           \
                    for (int k = 0; k < QPT; k++) {                             \
                        unsigned long long v =                                  \
                            fma2(ax[k], P.x, fma2(ay[k], P.y, fma2(az[k], Q.x, Q.y)));\
                        float2 vf = *reinterpret_cast<float2*>(&v);             \
                        mn0[k] = fminf(mn0[k], vf.x);                           \
                        mn1[k] = fminf(mn1[k], vf.y);                           \
                    }                                                           \
                }                                                               \
                p ^= 1;                                                         \
            }                                                                   \
        }

        // ---- phase A: fixed 128-target window at the warp's bin position ----
        float xref = __shfl_sync(0xffffffffu, q[0].x, 16);
        int pos = bs[binx(xref)];
        int a0 = max(0, pos - 64);
        int a1 = min(nt, pos + 64);
        SCAN_RANGE(a0, a1);

        // ---- certified window from the upper bounds ----
        float xmin = 3e38f, xmax = -3e38f;
#pragma unroll
        for (int k = 0; k < QPT; k++) {
            float dub = fmaxf(q[k].w + fminf(mn0[k], mn1[k]), 0.0f);
            float r = sqrtf(dub) * 1.0001f + 1e-6f;
            xmin = fminf(xmin, q[k].x - r);
            xmax = fmaxf(xmax, q[k].x + r);
        }
#pragma unroll
        for (int o = 16; o; o >>= 1) {
            xmin = fminf(xmin, __shfl_xor_sync(0xffffffffu, xmin, o));
            xmax = fmaxf(xmax, __shfl_xor_sync(0xffffffffu, xmax, o));
        }
        int b_lo = max(binx(xmin) - 1, 0);        // 1-bin margin: intra-bin disorder
        int b_hi = min(binx(xmax) + 2, NBINS);    // edge bins absorb clamped tails
        int w0 = bs[b_lo];
        int w1 = bs[b_hi];

        // ---- phase B: exact scan of the certified window (rescan of A is fine) ----
        SCAN_RANGE(w0, w1);
#undef SCAN_RANGE

#pragma unroll
        for (int k = 0; k < QPT; k++)
            if (valid[k]) dsum += q[k].w + fminf(mn0[k], mn1[k]);
    }

    // ---- block sum -> per-(dir,pair) sum -> fused finalize ----
#pragma unroll
    for (int o = 16; o; o >>= 1) dsum += __shfl_down_sync(0xffffffffu, dsum, o);
    __shared__ float wsum[NT / 32];
    if (lane == 0) wsum[wid] = dsum;
    __syncthreads();
    if (tid == 0) {
        float t = 0.0f;
#pragma unroll
        for (int wv = 0; wv < NT / 32; wv++) t += wsum[wv];
        atomicAdd(&g_sum[dir][pair], t);
        __threadfence();
        if (atomicAdd(&g_part[dir][pair], 1) == GXN - 1) {
            __threadfence();
            float c = (float)nq; if (c < 1.0f) c = 1.0f;
            g_sum[dir][pair] = g_sum[dir][pair] / c;     // convert to mean
            __threadfence();
            if (atomicAdd(&g_done, 1) == NPAIR * 2 - 1) {
                __threadfence();
                float cham[NPAIR];
#pragma unroll
                for (int p = 0; p < NPAIR; p++)
                    cham[p] = g_sum[0][p] + g_sum[1][p];
                // tensor[s][b] = cham[b*SDIM + s]; per_step[s] = mean over b
#pragma unroll
                for (int s2 = 0; s2 < SDIM; s2++) {
                    float acc = 0.0f;
#pragma unroll
                    for (int b = 0; b < BDIM; b++) {
                        float cv = cham[b * SDIM + s2];
                        out[SDIM + s2 * BDIM + b] = cv;
                        acc += cv;
                    }
                    out[s2] = acc / (float)BDIM;
                }
            }
        }
    }
}

extern "C" void kernel_launch(void* const* d_in, const int* in_sizes, int n_in,
                              void* d_out, int out_size) {
    const float* rv  = (const float*)d_in[0];
    const float* tgt = (const float*)d_in[1];
    // d_in[2] (mos_label) and d_in[3] (n_samples) are unused per the reference.

    init_kernel<<<NLIST * NBINS / NTP, NTP>>>();
    prep_kernel<<<dim3(HW / NTP, NPAIR), NTP>>>(rv, tgt);
    prefix_kernel<<<NLIST, NTP>>>();
    scatter_kernel<<<dim3(HW / NTP, NPAIR, 2), NTP>>>();
    nn_kernel<<<dim3(GXN, NPAIR, 2), NT>>>((float*)d_out);
}

// round 14
// speedup vs baseline: 1.0734x; 1.0734x over previous
#include <cuda_runtime.h>
#include <cuda_bf16.h>

// Problem shape (fixed by the dataset)
#define HH 64
#define WW 128
#define HW (HH * WW)     // 8192 points per image
#define NPAIR 8          // B*S = 2*4
#define SDIM 4
#define BDIM 2
#define NT 256

// 1-D sort bins over x
#define NBINS  512
#define XLO0   (-5.5f)
#define BW     (11.0f / 512.0f)
#define INV_BW (512.0f / 11.0f)
#define NLIST  16            // list = side*NPAIR + pair
#define GX     9             // query blocks per (dir,pair): 9*512 = 4608 queries
#define QPT    2
#define QBLK   (NT * QPT)    // 512 queries per block
#define TS     2             // window split; grid = 9*8*4 = 288 CTAs
#define TILE   512
#define NGRP   (TILE / 2)

#define FLT_MAX_BITS 0x7F7FFFFF

// ---------------- device scratch ----------------
__device__ float4 g_pts[2][NPAIR][HW];   // compacted, unsorted (x,y,z,||p||^2)
__device__ float4 g_sq[NLIST][HW];       // x-sorted, query form (x,y,z,n)
__device__ float4 g_st[NLIST][HW];       // x-sorted, target form (-2x,-2y,-2z,n)
__device__ int    g_bincnt[NLIST][NBINS];
__device__ int    g_bincur[NLIST][NBINS];
__device__ int    g_binstart[NLIST][NBINS + 1];
__device__ int    g_min[2][NPAIR][HW];   // per-sorted-query NN dist bits
__device__ int    g_cnt[2][NPAIR];
__device__ float  g_sum[2][NPAIR];
__device__ int    g_part[2][NPAIR];
__device__ int    g_done;

__device__ __forceinline__ int binx(float x) {
    int b = (int)floorf((x - XLO0) * INV_BW);
    return b < 0 ? 0 : (b > NBINS - 1 ? NBINS - 1 : b);
}
__device__ __forceinline__ unsigned long long splat2(float v) {
    unsigned long long r;
    asm("mov.b64 %0, {%1, %1};" : "=l"(r) : "f"(v));
    return r;
}
__device__ __forceinline__ unsigned long long fma2(unsigned long long a,
                                                   unsigned long long b,
                                                   unsigned long long c) {
    unsigned long long d;
    asm("fma.rn.f32x2 %0, %1, %2, %3;" : "=l"(d) : "l"(a), "l"(b), "l"(c));
    return d;
}

// ---------------- 1: zero per-call state ----------------
__global__ void init_kernel() {
    int i = blockIdx.x * blockDim.x + threadIdx.x;   // NLIST*NBINS = 8192 threads
    ((int*)g_bincnt)[i] = 0;
    if (i < 16) {
        ((int*)g_cnt)[i] = 0;
        ((float*)g_sum)[i] = 0.0f;
        ((int*)g_part)[i] = 0;
    }
    if (i == 0) g_done = 0;
}

// ---------------- 2: back-project + compact + x-histogram ----------------
__global__ void prep_kernel(const float* __restrict__ rv,
                            const float* __restrict__ tgt) {
    const int pair = blockIdx.y;
    const int tid = threadIdx.x;
    const int i = blockIdx.x * blockDim.x + tid;   // 0..8191
    const int h = i / WW;
    const int w = i % WW;
    const int wid = tid >> 5, lane = tid & 31;

    g_min[0][pair][i] = FLT_MAX_BITS;
    g_min[1][pair][i] = FLT_MAX_BITS;

    const float FOV_DOWN = -0.4363323129985824f;   // -25 deg
    const float FOV      = 0.4886921905584123f;    // 28 deg span
    const float PI_F     = 3.14159265358979323846f;

    float pitch = (1.0f - (h + 0.5f) / (float)HH) * FOV + FOV_DOWN;
    float yaw   = -(((w + 0.5f) / (float)WW) * 2.0f - 1.0f) * PI_F;
    float cp = cosf(pitch), sp = sinf(pitch);
    float cy = cosf(yaw),  sy = sinf(yaw);

    float r = rv[pair * HW + i];
    float px[2], py[2], pz[2];
    bool  pv[2];
    pv[0] = r > 0.0f;
    px[0] = r * cp * cy; py[0] = r * cp * sy; pz[0] = r * sp;

    const float* tp = tgt + (size_t)pair * 4 * HW + i;
    float t0 = tp[0];
    pv[1] = t0 > 0.0f;
    px[1] = tp[HW]; py[1] = tp[2 * HW]; pz[1] = tp[3 * HW];

    __shared__ int s_wcnt[2][NT / 32];
    __shared__ int s_woff[2][NT / 32];

    unsigned m[2];
#pragma unroll
    for (int s = 0; s < 2; s++) {
        m[s] = __ballot_sync(0xffffffffu, pv[s]);
        if (lane == 0) s_wcnt[s][wid] = __popc(m[s]);
    }
    __syncthreads();
    if (tid < 2) {
        int tot = 0;
        int off[NT / 32];
#pragma unroll
        for (int wv = 0; wv < NT / 32; wv++) { off[wv] = tot; tot += s_wcnt[tid][wv]; }
        int base = (tot > 0) ? atomicAdd(&g_cnt[tid][pair], tot) : 0;
#pragma unroll
        for (int wv = 0; wv < NT / 32; wv++) s_woff[tid][wv] = base + off[wv];
    }
    __syncthreads();
#pragma unroll
    for (int s = 0; s < 2; s++) {
        if (pv[s]) {
            int pos = s_woff[s][wid] + __popc(m[s] & ((1u << lane) - 1u));
            float n = px[s] * px[s] + py[s] * py[s] + pz[s] * pz[s];
            g_pts[s][pair][pos] = make_float4(px[s], py[s], pz[s], n);
            atomicAdd(&g_bincnt[s * NPAIR + pair][binx(px[s])], 1);
        }
    }
}

// ---------------- 3: exclusive prefix over bins (one block per list) ----------------
__global__ void prefix_kernel() {
    const int list = blockIdx.x;
    const int t = threadIdx.x;          // 256 threads
    const int PER = NBINS / 256;        // 2 bins per thread
    const int base = t * PER;

    int c[PER];
    int s = 0;
#pragma unroll
    for (int k = 0; k < PER; k++) { c[k] = g_bincnt[list][base + k]; s += c[k]; }

    __shared__ int sh[256];
    sh[t] = s;
    __syncthreads();
    for (int off = 1; off < 256; off <<= 1) {
        int v = (t >= off) ? sh[t - off] : 0;
        __syncthreads();
        sh[t] += v;
        __syncthreads();
    }
    int run = sh[t] - s;   // exclusive
#pragma unroll
    for (int k = 0; k < PER; k++) {
        g_binstart[list][base + k] = run;
        g_bincur[list][base + k] = run;
        run += c[k];
    }
    if (t == 255) g_binstart[list][NBINS] = run;
}

// ---------------- 4: scatter into x-sorted order ----------------
__global__ void scatter_kernel() {
    const int side = blockIdx.z, pair = blockIdx.y;
    const int list = side * NPAIR + pair;
    const int i = blockIdx.x * blockDim.x + threadIdx.x;
    if (i >= g_cnt[side][pair]) return;
    float4 p = g_pts[side][pair][i];
    int pos = atomicAdd(&g_bincur[list][binx(p.x)], 1);
    g_sq[list][pos] = p;
    g_st[list][pos] = make_float4(-2.0f * p.x, -2.0f * p.y, -2.0f * p.z, p.w);
}

// ---------------- 5: hybrid windowed NN (block tiles, warp skip) ----------------
__global__ void __launch_bounds__(NT) nn_kernel(float* __restrict__ out) {
    const int dir  = blockIdx.z >> 1;
    const int th   = blockIdx.z & 1;
    const int pair = blockIdx.y;
    const int qlist = dir * NPAIR + pair;
    const int tlist = (1 - dir) * NPAIR + pair;
    const int nq = g_cnt[dir][pair];
    const int nt = g_cnt[1 - dir][pair];
    const int tid = threadIdx.x, wid = tid >> 5, lane = tid & 31;
    const int qbase = blockIdx.x * QBLK;

    const float4* __restrict__ tg = g_st[tlist];
    const int*    __restrict__ bs = g_binstart[tlist];

    __shared__ float4 sP[NGRP];
    __shared__ float4 sQ[NGRP];
    __shared__ float  s_xref;
    __shared__ float  s_red[2][NT / 32];

    if (qbase < nq && nt > 0) {
        float4 q[QPT];
        unsigned long long ax[QPT], ay[QPT], az[QPT];
        bool valid[QPT];
        float mn0[QPT], mn1[QPT];
#pragma unroll
        for (int k = 0; k < QPT; k++) {
            int qi = qbase + k * NT + tid;
            valid[k] = qi < nq;
            q[k] = g_sq[qlist][min(qi, nq - 1)];
            ax[k] = splat2(q[k].x); ay[k] = splat2(q[k].y); az[k] = splat2(q[k].z);
            mn0[k] = 3e38f; mn1[k] = 3e38f;
        }
        if (tid == NT / 2) s_xref = q[0].x;   // block-representative x

        // SCAN over [LO,HI): block-shared pair-packed tiles; warp skip optional
#define SCAN(LO, HI, WSKIP, WLO, WHI)                                           \
        for (int j0 = (LO); j0 < (HI); j0 += TILE) {                            \
            __syncthreads();                                                    \
            {                                                                   \
                int ja = j0 + 2 * tid;                                          \
                float4 t0 = (ja     < (HI)) ? tg[ja]                            \
                                            : make_float4(0.f, 0.f, 0.f, 3e38f);\
                float4 t1 = (ja + 1 < (HI)) ? tg[ja + 1]                        \
                                            : make_float4(0.f, 0.f, 0.f, 3e38f);\
                sP[tid] = make_float4(t0.x, t1.x, t0.y, t1.y);                  \
                sQ[tid] = make_float4(t0.z, t1.z, t0.w, t1.w);                  \
            }                                                                   \
            __syncthreads();                                                    \
            if (!(WSKIP) || (j0 < (WHI) && j0 + TILE > (WLO))) {                \
                const ulonglong2* __restrict__ pP =                             \
                    reinterpret_cast<const ulonglong2*>(sP);                    \
                const ulonglong2* __restrict__ pQ =                             \
                    reinterpret_cast<const ulonglong2*>(sQ);                    \
                _Pragma("unroll 8")                                             \
                for (int g = 0; g < NGRP; g++) {                                \
                    ulonglong2 P = pP[g];                                       \
                    ulonglong2 Q = pQ[g];                                       \
                    _Pragma("unroll")                                           \
                    for (int k = 0; k < QPT; k++) {                             \
                        unsigned long long v =                                  \
                            fma2(ax[k], P.x, fma2(ay[k], P.y, fma2(az[k], Q.x, Q.y)));\
                        float2 vf = *reinterpret_cast<float2*>(&v);             \
                        mn0[k] = fminf(mn0[k], vf.x);                           \
                        mn1[k] = fminf(mn1[k], vf.y);                           \
                    }                                                           \
                }                                                               \
            }                                                                   \
        }

        // ---- phase A: one 512-target tile at the block's x-position ----
        __syncthreads();
        int pos = bs[binx(s_xref)];
        int a0 = max(0, pos - 256);
        int a1 = min(nt, a0 + TILE);
        SCAN(a0, a1, false, 0, 0);

        // ---- per-lane certified radius ----
        float xmn = 3e38f, xmx = -3e38f;
#pragma unroll
        for (int k = 0; k < QPT; k++) {
            float dub = fmaxf(q[k].w + fminf(mn0[k], mn1[k]), 0.0f);
            float r = sqrtf(dub) * 1.0001f + 1e-6f;
            xmn = fminf(xmn, q[k].x - r);
            xmx = fmaxf(xmx, q[k].x + r);
        }
        // warp window
        float wmn = xmn, wmx = xmx;
#pragma unroll
        for (int o = 16; o; o >>= 1) {
            wmn = fminf(wmn, __shfl_xor_sync(0xffffffffu, wmn, o));
            wmx = fmaxf(wmx, __shfl_xor_sync(0xffffffffu, wmx, o));
        }
        int w0w = bs[max(binx(wmn) - 1, 0)];
        int w1w = bs[min(binx(wmx) + 2, NBINS)];
        // block window
        if (lane == 0) { s_red[0][wid] = wmn; s_red[1][wid] = wmx; }
        __syncthreads();
        float bmn = 3e38f, bmx = -3e38f;
#pragma unroll
        for (int wv = 0; wv < NT / 32; wv++) {
            bmn = fminf(bmn, s_red[0][wv]);
            bmx = fmaxf(bmx, s_red[1][wv]);
        }
        int w0b = bs[max(binx(bmn) - 1, 0)];
        int w1b = bs[min(binx(bmx) + 2, NBINS)];

        // ---- phase B: th-half of the block window's tiles, warp-skipped ----
        int jlo = w0b & ~(TILE - 1);
        int ntile = (w1b > jlo) ? (w1b - jlo + TILE - 1) / TILE : 0;
        int half = (ntile + 1) >> 1;
        int tb = jlo + (th ? half * TILE : 0);
        int te = th ? w1b : min(w1b, jlo + half * TILE);
        SCAN(tb, te, true, w0w, w1w);
#undef SCAN

#pragma unroll
        for (int k = 0; k < QPT; k++) {
            if (valid[k]) {
                float d = q[k].w + fminf(mn0[k], mn1[k]);
                atomicMin(&g_min[dir][pair][qbase + k * NT + tid], __float_as_int(d));
            }
        }
    }

    // ---- completion: last block of (dir,pair) sums g_min; last overall finalizes ----
    __shared__ int s_last;
    __shared__ float wsum[NT / 32];
    if (tid == 0) {
        __threadfence();
        s_last = (atomicAdd(&g_part[dir][pair], 1) == GX * TS - 1) ? 1 : 0;
    }
    __syncthreads();
    if (!s_last) return;
    __threadfence();

    float s = 0.0f;
    for (int i = tid; i < nq; i += NT)
        s += __int_as_float(g_min[dir][pair][i]);
#pragma unroll
    for (int o = 16; o; o >>= 1) s += __shfl_down_sync(0xffffffffu, s, o);
    if (lane == 0) wsum[wid] = s;
    __syncthreads();
    if (tid == 0) {
        float t = 0.0f;
#pragma unroll
        for (int wv = 0; wv < NT / 32; wv++) t += wsum[wv];
        float c = (float)nq; if (c < 1.0f) c = 1.0f;
        g_sum[dir][pair] = t / c;
        __threadfence();
        if (atomicAdd(&g_done, 1) == NPAIR * 2 - 1) {
            __threadfence();
            float cham[NPAIR];
#pragma unroll
            for (int p = 0; p < NPAIR; p++)
                cham[p] = g_sum[0][p] + g_sum[1][p];
#pragma unroll
            for (int s2 = 0; s2 < SDIM; s2++) {
                float acc = 0.0f;
#pragma unroll
                for (int b = 0; b < BDIM; b++) {
                    float cv = cham[b * SDIM + s2];
                    out[SDIM + s2 * BDIM + b] = cv;
                    acc += cv;
                }
                out[s2] = acc / (float)BDIM;
            }
        }
    }
}

extern "C" void kernel_launch(void* const* d_in, const int* in_sizes, int n_in,
                              void* d_out, int out_size) {
    const float* rv  = (const float*)d_in[0];
    const float* tgt = (const float*)d_in[1];
    // d_in[2] (mos_label) and d_in[3] (n_samples) are unused per the reference.

    init_kernel<<<NLIST * NBINS / NT, NT>>>();
    prep_kernel<<<dim3(HW / NT, NPAIR), NT>>>(rv, tgt);
    prefix_kernel<<<NLIST, NT>>>();
    scatter_kernel<<<dim3(HW / NT, NPAIR, 2), NT>>>();
    nn_kernel<<<dim3(GX, NPAIR, 2 * TS), NT>>>((float*)d_out);
}